// round 13
// baseline (speedup 1.0000x reference)
#include <cuda_runtime.h>
#include <cuda_fp16.h>
#include <cstdint>
#include <cstring>

#define N_NODES_MAX 100000
#define EDGE_MAX    1600000
#define DIM 128

// bit-cast helpers (fold to register moves)
__device__ __forceinline__ unsigned h2_to_u32(__half2 h) {
    unsigned u; memcpy(&u, &h, 4); return u;
}
__device__ __forceinline__ __half2 u32_to_h2(unsigned u) {
    __half2 h; memcpy(&h, &u, 4); return h;
}
__device__ __forceinline__ uint32_t smem_u32(const void* p) {
    uint32_t a;
    asm("{ .reg .u64 t; cvta.to.shared.u64 t, %1; cvt.u32.u64 %0, t; }" : "=r"(a) : "l"(p));
    return a;
}

#define LDSM_X4(r0, r1, r2, r3, addr)                                         \
    asm volatile("ldmatrix.sync.aligned.m8n8.x4.shared.b16 {%0,%1,%2,%3}, [%4];" \
                 : "=r"(r0), "=r"(r1), "=r"(r2), "=r"(r3) : "r"(addr))

#define MMA16816(c, a0, a1, a2, a3, b0, b1)                                   \
    asm volatile("mma.sync.aligned.m16n8k16.row.col.f32.f16.f16.f32 "         \
                 "{%0,%1,%2,%3}, {%4,%5,%6,%7}, {%8,%9}, {%0,%1,%2,%3};"      \
                 : "+f"(c[0]), "+f"(c[1]), "+f"(c[2]), "+f"(c[3])             \
                 : "r"(a0), "r"(a1), "r"(a2), "r"(a3), "r"(b0), "r"(b1))

// scratch (allocation-free rule: __device__ globals)
__device__ __half   g_Th[(size_t)N_NODES_MAX * DIM];  // transformed features (fp16)
__device__ unsigned g_cnt[N_NODES_MAX];
__device__ unsigned g_off[N_NODES_MAX];
__device__ unsigned g_cur[N_NODES_MAX];
__device__ unsigned g_bsum[256];
__device__ uint2    g_sorted[EDGE_MAX];               // (src, weight_bits) sorted by dst

// ---------------------------------------------------------------------------
// Kernel 1: T = node_emb @ W^T via HMMA (fp16 in, f32 acc, fp16 out). (R8)
// ---------------------------------------------------------------------------
#define SMS 136  // smem row stride in halves

__global__ __launch_bounds__(256, 2)
void transform_mma_kernel(const float* __restrict__ E, const float* __restrict__ W, int n_rows)
{
    extern __shared__ __half sm[];
    __half* As = sm;               // [128][SMS]
    __half* Ws = sm + 128 * SMS;   // [128][SMS]

    const int tid  = threadIdx.x;
    const int row0 = blockIdx.x * 128;

#pragma unroll
    for (int i = 0; i < 16; i++) {
        int idx = tid + i * 256;
        int r   = idx >> 5;
        int c4  = idx & 31;
        float4 v = make_float4(0.f, 0.f, 0.f, 0.f);
        int er = row0 + r;
        if (er < n_rows) v = *reinterpret_cast<const float4*>(&E[(size_t)er * DIM + c4 * 4]);
        uint2 ue = make_uint2(h2_to_u32(__floats2half2_rn(v.x, v.y)),
                              h2_to_u32(__floats2half2_rn(v.z, v.w)));
        *reinterpret_cast<uint2*>(&As[r * SMS + c4 * 4]) = ue;

        float4 wv = *reinterpret_cast<const float4*>(&W[(size_t)r * DIM + c4 * 4]);
        uint2 uw = make_uint2(h2_to_u32(__floats2half2_rn(wv.x, wv.y)),
                              h2_to_u32(__floats2half2_rn(wv.z, wv.w)));
        *reinterpret_cast<uint2*>(&Ws[r * SMS + c4 * 4]) = uw;
    }
    __syncthreads();

    const int lane = tid & 31;
    const int warp = tid >> 5;
    const int r0   = warp * 16;

    uint32_t a_base = smem_u32(&As[(r0 + (lane & 15)) * SMS + ((lane >> 4) * 8)]);
    int brow = (lane & 7) + ((lane & 16) ? 8 : 0);
    int bcol = ((lane >> 3) & 1) * 8;
    uint32_t b_base = smem_u32(&Ws[brow * SMS + bcol]);

    float c[16][4];
#pragma unroll
    for (int j = 0; j < 16; j++)
#pragma unroll
        for (int q = 0; q < 4; q++) c[j][q] = 0.f;

#pragma unroll
    for (int k0 = 0; k0 < 128; k0 += 16) {
        uint32_t a0, a1, a2, a3;
        LDSM_X4(a0, a1, a2, a3, a_base + k0 * 2);
#pragma unroll
        for (int np = 0; np < 8; np++) {
            uint32_t b0, b1, b2, b3;
            LDSM_X4(b0, b1, b2, b3, b_base + (np * 16 * SMS + k0) * 2);
            MMA16816(c[2 * np],     a0, a1, a2, a3, b0, b1);
            MMA16816(c[2 * np + 1], a0, a1, a2, a3, b2, b3);
        }
    }

    const int g = lane >> 2, t = lane & 3;
    const int rowA = row0 + r0 + g;
    const int rowB = rowA + 8;
#pragma unroll
    for (int j = 0; j < 16; j++) {
        __half2 h01 = __floats2half2_rn(c[j][0], c[j][1]);
        __half2 h23 = __floats2half2_rn(c[j][2], c[j][3]);
        int col = j * 8 + 2 * t;
        if (rowA < n_rows)
            *reinterpret_cast<__half2*>(&g_Th[(size_t)rowA * DIM + col]) = h01;
        if (rowB < n_rows)
            *reinterpret_cast<__half2*>(&g_Th[(size_t)rowB * DIM + col]) = h23;
    }
}

// ---------------------------------------------------------------------------
// Sort pipeline: histogram -> scan1(shuffle) -> scan3(fused base) -> bucket
// ---------------------------------------------------------------------------
__global__ void hist_kernel(const int* __restrict__ dst, int n_edges)
{
    int i = blockIdx.x * blockDim.x + threadIdx.x;
    int e0 = i * 4;
    if (e0 + 4 <= n_edges) {
        int4 d4 = *reinterpret_cast<const int4*>(dst + e0);
        atomicAdd(&g_cnt[d4.x], 1u);
        atomicAdd(&g_cnt[d4.y], 1u);
        atomicAdd(&g_cnt[d4.z], 1u);
        atomicAdd(&g_cnt[d4.w], 1u);
    } else {
        for (int e = e0; e < n_edges; e++) atomicAdd(&g_cnt[dst[e]], 1u);
    }
}

__global__ __launch_bounds__(1024)
void scan1_kernel(int n)
{
    __shared__ unsigned wsum[32];
    const int t    = threadIdx.x;
    const int lane = t & 31;
    const int warp = t >> 5;
    int i = blockIdx.x * 1024 + t;
    unsigned v = (i < n) ? g_cnt[i] : 0u;

    unsigned x = v;
#pragma unroll
    for (int o = 1; o < 32; o <<= 1) {
        unsigned y = __shfl_up_sync(0xffffffffu, x, o);
        if (lane >= o) x += y;
    }
    if (lane == 31) wsum[warp] = x;
    __syncthreads();
    if (warp == 0) {
        unsigned s = wsum[lane];
#pragma unroll
        for (int o = 1; o < 32; o <<= 1) {
            unsigned y = __shfl_up_sync(0xffffffffu, s, o);
            if (lane >= o) s += y;
        }
        wsum[lane] = s;
    }
    __syncthreads();
    unsigned base = (warp > 0) ? wsum[warp - 1] : 0u;
    unsigned incl = x + base;
    if (i < n) g_off[i] = incl - v;
    if (t == 1023) g_bsum[blockIdx.x] = incl;
}

__global__ __launch_bounds__(1024)
void scan3_kernel(int n)
{
    __shared__ unsigned sbase;
    int t = threadIdx.x;
    if (t < 32) {
        unsigned s = 0;
        int bid = blockIdx.x;
        for (int b = t; b < bid; b += 32) s += g_bsum[b];
#pragma unroll
        for (int o = 16; o; o >>= 1) s += __shfl_down_sync(0xffffffffu, s, o);
        if (t == 0) sbase = s;
    }
    __syncthreads();
    int i = blockIdx.x * 1024 + t;
    if (i < n) {
        unsigned o = g_off[i] + sbase;
        g_off[i] = o;
        g_cur[i] = o;
    }
}

__global__ void bucket_kernel(const int* __restrict__ src,
                              const int* __restrict__ dst,
                              const float* __restrict__ ew,
                              int n_edges)
{
    int i = blockIdx.x * blockDim.x + threadIdx.x;
    int e0 = i * 4;
    if (e0 + 4 <= n_edges) {
        int4   s4 = *reinterpret_cast<const int4*>(src + e0);
        int4   d4 = *reinterpret_cast<const int4*>(dst + e0);
        float4 w4 = *reinterpret_cast<const float4*>(ew + e0);
        unsigned p0 = atomicAdd(&g_cur[d4.x], 1u);
        unsigned p1 = atomicAdd(&g_cur[d4.y], 1u);
        unsigned p2 = atomicAdd(&g_cur[d4.z], 1u);
        unsigned p3 = atomicAdd(&g_cur[d4.w], 1u);
        g_sorted[p0] = make_uint2((unsigned)s4.x, __float_as_uint(w4.x));
        g_sorted[p1] = make_uint2((unsigned)s4.y, __float_as_uint(w4.y));
        g_sorted[p2] = make_uint2((unsigned)s4.z, __float_as_uint(w4.z));
        g_sorted[p3] = make_uint2((unsigned)s4.w, __float_as_uint(w4.w));
    } else {
        for (int e = e0; e < n_edges; e++) {
            int d = dst[e];
            unsigned pos = atomicAdd(&g_cur[d], 1u);
            g_sorted[pos] = make_uint2((unsigned)src[e], __float_as_uint(ew[e]));
        }
    }
}

// ---------------------------------------------------------------------------
// Aggregation: one warp per dst node; LDG.128 half-warp rows — lanes 0-15
// cover edge e's 256B row at 16B/lane, lanes 16-31 cover edge e+1's. One
// LDG.128 instruction moves TWO edges. Cross-half shfl_xor(16) reduce at end.
// ---------------------------------------------------------------------------
__global__ __launch_bounds__(256)
void agg_kernel(float* __restrict__ out, int n_nodes, int n_edges)
{
    int node = (int)((blockIdx.x * (unsigned)blockDim.x + threadIdx.x) >> 5);
    int lane = threadIdx.x & 31;
    if (node >= n_nodes) return;

    const int half = lane >> 4;        // 0 or 1: which edge of the pair
    const int l16  = lane & 15;        // 16B chunk within the 256B row

    unsigned start = g_off[node];
    unsigned end   = (node + 1 < n_nodes) ? g_off[node + 1] : (unsigned)n_edges;

    // each lane accumulates dims [l16*8, l16*8+8) as 2 float4; two edge-sets
    float4 a0 = make_float4(0.f, 0.f, 0.f, 0.f);
    float4 a1 = a0, b0v = a0, b1v = a0;

    unsigned e = start;
    for (; e + 4 <= end; e += 4) {
        uint2 m0 = g_sorted[e + 0];
        uint2 m1 = g_sorted[e + 1];
        uint2 m2 = g_sorted[e + 2];
        uint2 m3 = g_sorted[e + 3];
        unsigned sA = half ? m1.x : m0.x;
        unsigned sB = half ? m3.x : m2.x;
        float wA = __uint_as_float(half ? m1.y : m0.y);
        float wB = __uint_as_float(half ? m3.y : m2.y);

        uint4 hA = *reinterpret_cast<const uint4*>(&g_Th[(size_t)sA * DIM + l16 * 8]);
        uint4 hB = *reinterpret_cast<const uint4*>(&g_Th[(size_t)sB * DIM + l16 * 8]);

        float2 t;
        t = __half22float2(u32_to_h2(hA.x)); a0.x += t.x * wA; a0.y += t.y * wA;
        t = __half22float2(u32_to_h2(hA.y)); a0.z += t.x * wA; a0.w += t.y * wA;
        t = __half22float2(u32_to_h2(hA.z)); a1.x += t.x * wA; a1.y += t.y * wA;
        t = __half22float2(u32_to_h2(hA.w)); a1.z += t.x * wA; a1.w += t.y * wA;
        t = __half22float2(u32_to_h2(hB.x)); b0v.x += t.x * wB; b0v.y += t.y * wB;
        t = __half22float2(u32_to_h2(hB.y)); b0v.z += t.x * wB; b0v.w += t.y * wB;
        t = __half22float2(u32_to_h2(hB.z)); b1v.x += t.x * wB; b1v.y += t.y * wB;
        t = __half22float2(u32_to_h2(hB.w)); b1v.z += t.x * wB; b1v.w += t.y * wB;
    }
    // pair tail
    for (; e + 2 <= end; e += 2) {
        uint2 m0 = g_sorted[e + 0];
        uint2 m1 = g_sorted[e + 1];
        unsigned sA = half ? m1.x : m0.x;
        float wA = __uint_as_float(half ? m1.y : m0.y);
        uint4 hA = *reinterpret_cast<const uint4*>(&g_Th[(size_t)sA * DIM + l16 * 8]);
        float2 t;
        t = __half22float2(u32_to_h2(hA.x)); a0.x += t.x * wA; a0.y += t.y * wA;
        t = __half22float2(u32_to_h2(hA.y)); a0.z += t.x * wA; a0.w += t.y * wA;
        t = __half22float2(u32_to_h2(hA.z)); a1.x += t.x * wA; a1.y += t.y * wA;
        t = __half22float2(u32_to_h2(hA.w)); a1.z += t.x * wA; a1.w += t.y * wA;
    }
    // single tail: half 1 contributes zero weight (same address, safe)
    if (e < end) {
        uint2 m = g_sorted[e];
        float wA = half ? 0.f : __uint_as_float(m.y);
        uint4 hA = *reinterpret_cast<const uint4*>(&g_Th[(size_t)m.x * DIM + l16 * 8]);
        float2 t;
        t = __half22float2(u32_to_h2(hA.x)); a0.x += t.x * wA; a0.y += t.y * wA;
        t = __half22float2(u32_to_h2(hA.y)); a0.z += t.x * wA; a0.w += t.y * wA;
        t = __half22float2(u32_to_h2(hA.z)); a1.x += t.x * wA; a1.y += t.y * wA;
        t = __half22float2(u32_to_h2(hA.w)); a1.z += t.x * wA; a1.w += t.y * wA;
    }

    // combine edge-sets, then reduce across half-warps (lane i <-> i+16 hold
    // the SAME dims for different edge subsets)
    a0.x += b0v.x; a0.y += b0v.y; a0.z += b0v.z; a0.w += b0v.w;
    a1.x += b1v.x; a1.y += b1v.y; a1.z += b1v.z; a1.w += b1v.w;

    a0.x += __shfl_xor_sync(0xffffffffu, a0.x, 16);
    a0.y += __shfl_xor_sync(0xffffffffu, a0.y, 16);
    a0.z += __shfl_xor_sync(0xffffffffu, a0.z, 16);
    a0.w += __shfl_xor_sync(0xffffffffu, a0.w, 16);
    a1.x += __shfl_xor_sync(0xffffffffu, a1.x, 16);
    a1.y += __shfl_xor_sync(0xffffffffu, a1.y, 16);
    a1.z += __shfl_xor_sync(0xffffffffu, a1.z, 16);
    a1.w += __shfl_xor_sync(0xffffffffu, a1.w, 16);

    if (half == 0) {
        *reinterpret_cast<float4*>(&out[(size_t)node * DIM + l16 * 8])     = a0;
        *reinterpret_cast<float4*>(&out[(size_t)node * DIM + l16 * 8 + 4]) = a1;
    }
}

// ---------------------------------------------------------------------------
// Launch: GEMM on side stream overlapped with sort chain (fork/join).
// ---------------------------------------------------------------------------
extern "C" void kernel_launch(void* const* d_in, const int* in_sizes, int n_in,
                              void* d_out, int out_size)
{
    const float* node_emb = (const float*)d_in[0];
    const float* ew       = (const float*)d_in[1];
    const int*   src      = (const int*)d_in[2];
    const int*   dst      = (const int*)d_in[3];
    const float* W        = (const float*)d_in[4];
    float*       out      = (float*)d_out;

    const int n_nodes = in_sizes[0] / DIM;
    const int n_edges = in_sizes[1];

    void* cnt_ptr = nullptr;
    cudaGetSymbolAddress(&cnt_ptr, g_cnt);

    cudaStream_t s;
    cudaStreamCreateWithFlags(&s, cudaStreamNonBlocking);
    cudaEvent_t evFork, evJoin;
    cudaEventCreateWithFlags(&evFork, cudaEventDisableTiming);
    cudaEventCreateWithFlags(&evJoin, cudaEventDisableTiming);

    cudaEventRecord(evFork, 0);
    cudaStreamWaitEvent(s, evFork, 0);

    // --- side stream: tensor-core transform ---
    const int smem_bytes = 2 * 128 * SMS * (int)sizeof(__half);  // 69632
    cudaFuncSetAttribute(transform_mma_kernel,
                         cudaFuncAttributeMaxDynamicSharedMemorySize, smem_bytes);
    int gemm_blocks = (n_nodes + 127) / 128;
    transform_mma_kernel<<<gemm_blocks, 256, smem_bytes, s>>>(node_emb, W, n_nodes);
    cudaEventRecord(evJoin, s);

    // --- main stream: sort pipeline ---
    cudaMemsetAsync(cnt_ptr, 0, (size_t)n_nodes * sizeof(unsigned));
    int eb4 = (n_edges / 4 + 255) / 256 + 1;
    hist_kernel<<<eb4, 256>>>(dst, n_edges);
    int nchunks = (n_nodes + 1023) / 1024;
    scan1_kernel<<<nchunks, 1024>>>(n_nodes);
    scan3_kernel<<<nchunks, 1024>>>(n_nodes);
    bucket_kernel<<<eb4, 256>>>(src, dst, ew, n_edges);

    cudaStreamWaitEvent(0, evJoin, 0);
    int ab = (n_nodes * 32 + 255) / 256;
    agg_kernel<<<ab, 256>>>(out, n_nodes, n_edges);

    cudaStreamCaptureStatus cap = cudaStreamCaptureStatusNone;
    cudaStreamIsCapturing(s, &cap);
    if (cap == cudaStreamCaptureStatusNone) {
        cudaEventDestroy(evFork);
        cudaEventDestroy(evJoin);
        cudaStreamDestroy(s);
    }
}

// round 14
// speedup vs baseline: 1.0015x; 1.0015x over previous
#include <cuda_runtime.h>
#include <cuda_fp16.h>
#include <cstdint>
#include <cstring>

#define N_NODES_MAX 100000
#define EDGE_MAX    1600000
#define DIM 128

// bit-cast helpers (fold to register moves)
__device__ __forceinline__ unsigned h2_to_u32(__half2 h) {
    unsigned u; memcpy(&u, &h, 4); return u;
}
__device__ __forceinline__ __half2 u32_to_h2(unsigned u) {
    __half2 h; memcpy(&h, &u, 4); return h;
}
__device__ __forceinline__ uint32_t smem_u32(const void* p) {
    uint32_t a;
    asm("{ .reg .u64 t; cvta.to.shared.u64 t, %1; cvt.u32.u64 %0, t; }" : "=r"(a) : "l"(p));
    return a;
}

#define LDSM_X4(r0, r1, r2, r3, addr)                                         \
    asm volatile("ldmatrix.sync.aligned.m8n8.x4.shared.b16 {%0,%1,%2,%3}, [%4];" \
                 : "=r"(r0), "=r"(r1), "=r"(r2), "=r"(r3) : "r"(addr))

#define MMA16816(c, a0, a1, a2, a3, b0, b1)                                   \
    asm volatile("mma.sync.aligned.m16n8k16.row.col.f32.f16.f16.f32 "         \
                 "{%0,%1,%2,%3}, {%4,%5,%6,%7}, {%8,%9}, {%0,%1,%2,%3};"      \
                 : "+f"(c[0]), "+f"(c[1]), "+f"(c[2]), "+f"(c[3])             \
                 : "r"(a0), "r"(a1), "r"(a2), "r"(a3), "r"(b0), "r"(b1))

// scratch (allocation-free rule: __device__ globals)
__device__ __half   g_Th[(size_t)N_NODES_MAX * DIM];  // transformed features (fp16)
__device__ unsigned g_cnt[N_NODES_MAX];
__device__ unsigned g_off[N_NODES_MAX];
__device__ unsigned g_cur[N_NODES_MAX];
__device__ unsigned g_bsum[256];
__device__ uint2    g_sorted[EDGE_MAX];               // (src, weight_bits) sorted by dst

// ---------------------------------------------------------------------------
// Kernel 1: T = node_emb @ W^T via HMMA, 128x64 tile per block (N split in 2).
// ~70 regs/thread instead of 128 -> sort kernels can co-reside on the SM,
// making the side-stream overlap real instead of wave-interleaved.
// ---------------------------------------------------------------------------
#define SMS 136  // smem row stride in halves

__global__ __launch_bounds__(256, 2)
void transform_mma_kernel(const float* __restrict__ E, const float* __restrict__ W, int n_rows)
{
    extern __shared__ __half sm[];
    __half* As = sm;               // [128][SMS]
    __half* Ws = sm + 128 * SMS;   // [64][SMS]   (this block's 64 W rows)

    const int tid  = threadIdx.x;
    const int row0 = blockIdx.x * 128;
    const int col0 = blockIdx.y * 64;

    // E tile: 128 rows x 128 cols fp32 -> fp16 (zero-padded past n_rows)
#pragma unroll
    for (int i = 0; i < 16; i++) {
        int idx = tid + i * 256;       // 0..4095
        int r   = idx >> 5;            // 0..127
        int c4  = idx & 31;
        float4 v = make_float4(0.f, 0.f, 0.f, 0.f);
        int er = row0 + r;
        if (er < n_rows) v = *reinterpret_cast<const float4*>(&E[(size_t)er * DIM + c4 * 4]);
        uint2 ue = make_uint2(h2_to_u32(__floats2half2_rn(v.x, v.y)),
                              h2_to_u32(__floats2half2_rn(v.z, v.w)));
        *reinterpret_cast<uint2*>(&As[r * SMS + c4 * 4]) = ue;
    }
    // W half-tile: rows [col0, col0+64) x 128 k
#pragma unroll
    for (int i = 0; i < 8; i++) {
        int idx = tid + i * 256;       // 0..2047
        int r   = idx >> 5;            // 0..63
        int c4  = idx & 31;
        float4 wv = *reinterpret_cast<const float4*>(&W[(size_t)(col0 + r) * DIM + c4 * 4]);
        uint2 uw = make_uint2(h2_to_u32(__floats2half2_rn(wv.x, wv.y)),
                              h2_to_u32(__floats2half2_rn(wv.z, wv.w)));
        *reinterpret_cast<uint2*>(&Ws[r * SMS + c4 * 4]) = uw;
    }
    __syncthreads();

    const int lane = tid & 31;
    const int warp = tid >> 5;
    const int r0   = warp * 16;

    uint32_t a_base = smem_u32(&As[(r0 + (lane & 15)) * SMS + ((lane >> 4) * 8)]);
    int brow = (lane & 7) + ((lane & 16) ? 8 : 0);
    int bcol = ((lane >> 3) & 1) * 8;
    uint32_t b_base = smem_u32(&Ws[brow * SMS + bcol]);

    float c[8][4];
#pragma unroll
    for (int j = 0; j < 8; j++)
#pragma unroll
        for (int q = 0; q < 4; q++) c[j][q] = 0.f;

#pragma unroll
    for (int k0 = 0; k0 < 128; k0 += 16) {
        uint32_t a0, a1, a2, a3;
        LDSM_X4(a0, a1, a2, a3, a_base + k0 * 2);
#pragma unroll
        for (int np = 0; np < 4; np++) {
            uint32_t b0, b1, b2, b3;
            LDSM_X4(b0, b1, b2, b3, b_base + (np * 16 * SMS + k0) * 2);
            MMA16816(c[2 * np],     a0, a1, a2, a3, b0, b1);
            MMA16816(c[2 * np + 1], a0, a1, a2, a3, b2, b3);
        }
    }

    const int g = lane >> 2, t = lane & 3;
    const int rowA = row0 + r0 + g;
    const int rowB = rowA + 8;
#pragma unroll
    for (int j = 0; j < 8; j++) {
        __half2 h01 = __floats2half2_rn(c[j][0], c[j][1]);
        __half2 h23 = __floats2half2_rn(c[j][2], c[j][3]);
        int col = col0 + j * 8 + 2 * t;
        if (rowA < n_rows)
            *reinterpret_cast<__half2*>(&g_Th[(size_t)rowA * DIM + col]) = h01;
        if (rowB < n_rows)
            *reinterpret_cast<__half2*>(&g_Th[(size_t)rowB * DIM + col]) = h23;
    }
}

// ---------------------------------------------------------------------------
// Sort pipeline: histogram -> scan1(shuffle) -> scan3(fused base) -> bucket
// ---------------------------------------------------------------------------
__global__ void hist_kernel(const int* __restrict__ dst, int n_edges)
{
    int i = blockIdx.x * blockDim.x + threadIdx.x;
    int e0 = i * 4;
    if (e0 + 4 <= n_edges) {
        int4 d4 = *reinterpret_cast<const int4*>(dst + e0);
        atomicAdd(&g_cnt[d4.x], 1u);
        atomicAdd(&g_cnt[d4.y], 1u);
        atomicAdd(&g_cnt[d4.z], 1u);
        atomicAdd(&g_cnt[d4.w], 1u);
    } else {
        for (int e = e0; e < n_edges; e++) atomicAdd(&g_cnt[dst[e]], 1u);
    }
}

__global__ __launch_bounds__(1024)
void scan1_kernel(int n)
{
    __shared__ unsigned wsum[32];
    const int t    = threadIdx.x;
    const int lane = t & 31;
    const int warp = t >> 5;
    int i = blockIdx.x * 1024 + t;
    unsigned v = (i < n) ? g_cnt[i] : 0u;

    unsigned x = v;
#pragma unroll
    for (int o = 1; o < 32; o <<= 1) {
        unsigned y = __shfl_up_sync(0xffffffffu, x, o);
        if (lane >= o) x += y;
    }
    if (lane == 31) wsum[warp] = x;
    __syncthreads();
    if (warp == 0) {
        unsigned s = wsum[lane];
#pragma unroll
        for (int o = 1; o < 32; o <<= 1) {
            unsigned y = __shfl_up_sync(0xffffffffu, s, o);
            if (lane >= o) s += y;
        }
        wsum[lane] = s;
    }
    __syncthreads();
    unsigned base = (warp > 0) ? wsum[warp - 1] : 0u;
    unsigned incl = x + base;
    if (i < n) g_off[i] = incl - v;
    if (t == 1023) g_bsum[blockIdx.x] = incl;
}

__global__ __launch_bounds__(1024)
void scan3_kernel(int n)
{
    __shared__ unsigned sbase;
    int t = threadIdx.x;
    if (t < 32) {
        unsigned s = 0;
        int bid = blockIdx.x;
        for (int b = t; b < bid; b += 32) s += g_bsum[b];
#pragma unroll
        for (int o = 16; o; o >>= 1) s += __shfl_down_sync(0xffffffffu, s, o);
        if (t == 0) sbase = s;
    }
    __syncthreads();
    int i = blockIdx.x * 1024 + t;
    if (i < n) {
        unsigned o = g_off[i] + sbase;
        g_off[i] = o;
        g_cur[i] = o;
    }
}

__global__ void bucket_kernel(const int* __restrict__ src,
                              const int* __restrict__ dst,
                              const float* __restrict__ ew,
                              int n_edges)
{
    int i = blockIdx.x * blockDim.x + threadIdx.x;
    int e0 = i * 4;
    if (e0 + 4 <= n_edges) {
        int4   s4 = *reinterpret_cast<const int4*>(src + e0);
        int4   d4 = *reinterpret_cast<const int4*>(dst + e0);
        float4 w4 = *reinterpret_cast<const float4*>(ew + e0);
        unsigned p0 = atomicAdd(&g_cur[d4.x], 1u);
        unsigned p1 = atomicAdd(&g_cur[d4.y], 1u);
        unsigned p2 = atomicAdd(&g_cur[d4.z], 1u);
        unsigned p3 = atomicAdd(&g_cur[d4.w], 1u);
        g_sorted[p0] = make_uint2((unsigned)s4.x, __float_as_uint(w4.x));
        g_sorted[p1] = make_uint2((unsigned)s4.y, __float_as_uint(w4.y));
        g_sorted[p2] = make_uint2((unsigned)s4.z, __float_as_uint(w4.z));
        g_sorted[p3] = make_uint2((unsigned)s4.w, __float_as_uint(w4.w));
    } else {
        for (int e = e0; e < n_edges; e++) {
            int d = dst[e];
            unsigned pos = atomicAdd(&g_cur[d], 1u);
            g_sorted[pos] = make_uint2((unsigned)src[e], __float_as_uint(ew[e]));
        }
    }
}

// ---------------------------------------------------------------------------
// Aggregation: EXACT R8 champion loop — one warp per dst node, 4x uint2
// metadata broadcast loads, 4 independent uint2 gathers, 4 accumulators.
// ---------------------------------------------------------------------------
__device__ __forceinline__ void agg_one(float4& acc, unsigned srcn, unsigned wbits, int lane)
{
    uint2 h = *reinterpret_cast<const uint2*>(&g_Th[(size_t)srcn * DIM + lane * 4]);
    float w = __uint_as_float(wbits);
    float2 va = __half22float2(u32_to_h2(h.x));
    float2 vb = __half22float2(u32_to_h2(h.y));
    acc.x += va.x * w; acc.y += va.y * w; acc.z += vb.x * w; acc.w += vb.y * w;
}

__global__ __launch_bounds__(256)
void agg_kernel(float* __restrict__ out, int n_nodes, int n_edges)
{
    int node = (int)((blockIdx.x * (unsigned)blockDim.x + threadIdx.x) >> 5);
    int lane = threadIdx.x & 31;
    if (node >= n_nodes) return;

    unsigned start = g_off[node];
    unsigned end   = (node + 1 < n_nodes) ? g_off[node + 1] : (unsigned)n_edges;

    float4 a0 = make_float4(0.f, 0.f, 0.f, 0.f);
    float4 a1 = a0, a2 = a0, a3 = a0;

    unsigned e = start;
    for (; e + 4 <= end; e += 4) {
        uint2 m0 = g_sorted[e + 0];
        uint2 m1 = g_sorted[e + 1];
        uint2 m2 = g_sorted[e + 2];
        uint2 m3 = g_sorted[e + 3];
        uint2 h0 = *reinterpret_cast<const uint2*>(&g_Th[(size_t)m0.x * DIM + lane * 4]);
        uint2 h1 = *reinterpret_cast<const uint2*>(&g_Th[(size_t)m1.x * DIM + lane * 4]);
        uint2 h2 = *reinterpret_cast<const uint2*>(&g_Th[(size_t)m2.x * DIM + lane * 4]);
        uint2 h3 = *reinterpret_cast<const uint2*>(&g_Th[(size_t)m3.x * DIM + lane * 4]);
        float w0 = __uint_as_float(m0.y), w1 = __uint_as_float(m1.y);
        float w2 = __uint_as_float(m2.y), w3 = __uint_as_float(m3.y);
        float2 t;
        t = __half22float2(u32_to_h2(h0.x)); a0.x += t.x * w0; a0.y += t.y * w0;
        t = __half22float2(u32_to_h2(h0.y)); a0.z += t.x * w0; a0.w += t.y * w0;
        t = __half22float2(u32_to_h2(h1.x)); a1.x += t.x * w1; a1.y += t.y * w1;
        t = __half22float2(u32_to_h2(h1.y)); a1.z += t.x * w1; a1.w += t.y * w1;
        t = __half22float2(u32_to_h2(h2.x)); a2.x += t.x * w2; a2.y += t.y * w2;
        t = __half22float2(u32_to_h2(h2.y)); a2.z += t.x * w2; a2.w += t.y * w2;
        t = __half22float2(u32_to_h2(h3.x)); a3.x += t.x * w3; a3.y += t.y * w3;
        t = __half22float2(u32_to_h2(h3.y)); a3.z += t.x * w3; a3.w += t.y * w3;
    }
    for (; e < end; e++) agg_one(a0, g_sorted[e].x, g_sorted[e].y, lane);

    float4 r;
    r.x = (a0.x + a1.x) + (a2.x + a3.x);
    r.y = (a0.y + a1.y) + (a2.y + a3.y);
    r.z = (a0.z + a1.z) + (a2.z + a3.z);
    r.w = (a0.w + a1.w) + (a2.w + a3.w);
    *reinterpret_cast<float4*>(&out[(size_t)node * DIM + lane * 4]) = r;
}

// ---------------------------------------------------------------------------
// Launch: GEMM on side stream overlapped with sort chain (fork/join).
// ---------------------------------------------------------------------------
extern "C" void kernel_launch(void* const* d_in, const int* in_sizes, int n_in,
                              void* d_out, int out_size)
{
    const float* node_emb = (const float*)d_in[0];
    const float* ew       = (const float*)d_in[1];
    const int*   src      = (const int*)d_in[2];
    const int*   dst      = (const int*)d_in[3];
    const float* W        = (const float*)d_in[4];
    float*       out      = (float*)d_out;

    const int n_nodes = in_sizes[0] / DIM;
    const int n_edges = in_sizes[1];

    void* cnt_ptr = nullptr;
    cudaGetSymbolAddress(&cnt_ptr, g_cnt);

    cudaStream_t s;
    cudaStreamCreateWithFlags(&s, cudaStreamNonBlocking);
    cudaEvent_t evFork, evJoin;
    cudaEventCreateWithFlags(&evFork, cudaEventDisableTiming);
    cudaEventCreateWithFlags(&evJoin, cudaEventDisableTiming);

    cudaEventRecord(evFork, 0);
    cudaStreamWaitEvent(s, evFork, 0);

    // --- side stream: tensor-core transform (128x64 tiles, low regs) ---
    const int smem_bytes = (128 + 64) * SMS * (int)sizeof(__half);  // 52224
    cudaFuncSetAttribute(transform_mma_kernel,
                         cudaFuncAttributeMaxDynamicSharedMemorySize, smem_bytes);
    dim3 gemm_grid((n_nodes + 127) / 128, 2);
    transform_mma_kernel<<<gemm_grid, 256, smem_bytes, s>>>(node_emb, W, n_nodes);
    cudaEventRecord(evJoin, s);

    // --- main stream: sort pipeline ---
    cudaMemsetAsync(cnt_ptr, 0, (size_t)n_nodes * sizeof(unsigned));
    int eb4 = (n_edges / 4 + 255) / 256 + 1;
    hist_kernel<<<eb4, 256>>>(dst, n_edges);
    int nchunks = (n_nodes + 1023) / 1024;
    scan1_kernel<<<nchunks, 1024>>>(n_nodes);
    scan3_kernel<<<nchunks, 1024>>>(n_nodes);
    bucket_kernel<<<eb4, 256>>>(src, dst, ew, n_edges);

    cudaStreamWaitEvent(0, evJoin, 0);
    int ab = (n_nodes * 32 + 255) / 256;
    agg_kernel<<<ab, 256>>>(out, n_nodes, n_edges);

    cudaStreamCaptureStatus cap = cudaStreamCaptureStatusNone;
    cudaStreamIsCapturing(s, &cap);
    if (cap == cudaStreamCaptureStatusNone) {
        cudaEventDestroy(evFork);
        cudaEventDestroy(evJoin);
        cudaStreamDestroy(s);
    }
}

// round 15
// speedup vs baseline: 1.0139x; 1.0124x over previous
#include <cuda_runtime.h>
#include <cuda_fp16.h>
#include <cstdint>
#include <cstring>

#define N_NODES_MAX 100000
#define EDGE_MAX    1600000
#define DIM 128

// bit-cast helpers (fold to register moves)
__device__ __forceinline__ unsigned h2_to_u32(__half2 h) {
    unsigned u; memcpy(&u, &h, 4); return u;
}
__device__ __forceinline__ __half2 u32_to_h2(unsigned u) {
    __half2 h; memcpy(&h, &u, 4); return h;
}
__device__ __forceinline__ uint32_t smem_u32(const void* p) {
    uint32_t a;
    asm("{ .reg .u64 t; cvta.to.shared.u64 t, %1; cvt.u32.u64 %0, t; }" : "=r"(a) : "l"(p));
    return a;
}

#define LDSM_X4(r0, r1, r2, r3, addr)                                         \
    asm volatile("ldmatrix.sync.aligned.m8n8.x4.shared.b16 {%0,%1,%2,%3}, [%4];" \
                 : "=r"(r0), "=r"(r1), "=r"(r2), "=r"(r3) : "r"(addr))

#define MMA16816(c, a0, a1, a2, a3, b0, b1)                                   \
    asm volatile("mma.sync.aligned.m16n8k16.row.col.f32.f16.f16.f32 "         \
                 "{%0,%1,%2,%3}, {%4,%5,%6,%7}, {%8,%9}, {%0,%1,%2,%3};"      \
                 : "+f"(c[0]), "+f"(c[1]), "+f"(c[2]), "+f"(c[3])             \
                 : "r"(a0), "r"(a1), "r"(a2), "r"(a3), "r"(b0), "r"(b1))

// scratch (allocation-free rule: __device__ globals; zero-initialized at load)
__device__ __half             g_Th[(size_t)N_NODES_MAX * DIM];  // transformed features
__device__ unsigned           g_cnt[N_NODES_MAX];
__device__ unsigned           g_off[N_NODES_MAX];
__device__ unsigned           g_cur[N_NODES_MAX];
__device__ unsigned long long g_state[256];                     // lookback: (flag<<32)|sum
__device__ uint2              g_sorted[EDGE_MAX];               // (src, w_bits) sorted by dst

// ---------------------------------------------------------------------------
// Kernel 1: T = node_emb @ W^T via HMMA (fp16 in, f32 acc, fp16 out). EXACT R8.
// ---------------------------------------------------------------------------
#define SMS 136  // smem row stride in halves

__global__ __launch_bounds__(256, 2)
void transform_mma_kernel(const float* __restrict__ E, const float* __restrict__ W, int n_rows)
{
    extern __shared__ __half sm[];
    __half* As = sm;               // [128][SMS]
    __half* Ws = sm + 128 * SMS;   // [128][SMS]

    const int tid  = threadIdx.x;
    const int row0 = blockIdx.x * 128;

#pragma unroll
    for (int i = 0; i < 16; i++) {
        int idx = tid + i * 256;
        int r   = idx >> 5;
        int c4  = idx & 31;
        float4 v = make_float4(0.f, 0.f, 0.f, 0.f);
        int er = row0 + r;
        if (er < n_rows) v = *reinterpret_cast<const float4*>(&E[(size_t)er * DIM + c4 * 4]);
        uint2 ue = make_uint2(h2_to_u32(__floats2half2_rn(v.x, v.y)),
                              h2_to_u32(__floats2half2_rn(v.z, v.w)));
        *reinterpret_cast<uint2*>(&As[r * SMS + c4 * 4]) = ue;

        float4 wv = *reinterpret_cast<const float4*>(&W[(size_t)r * DIM + c4 * 4]);
        uint2 uw = make_uint2(h2_to_u32(__floats2half2_rn(wv.x, wv.y)),
                              h2_to_u32(__floats2half2_rn(wv.z, wv.w)));
        *reinterpret_cast<uint2*>(&Ws[r * SMS + c4 * 4]) = uw;
    }
    __syncthreads();

    const int lane = tid & 31;
    const int warp = tid >> 5;
    const int r0   = warp * 16;

    uint32_t a_base = smem_u32(&As[(r0 + (lane & 15)) * SMS + ((lane >> 4) * 8)]);
    int brow = (lane & 7) + ((lane & 16) ? 8 : 0);
    int bcol = ((lane >> 3) & 1) * 8;
    uint32_t b_base = smem_u32(&Ws[brow * SMS + bcol]);

    float c[16][4];
#pragma unroll
    for (int j = 0; j < 16; j++)
#pragma unroll
        for (int q = 0; q < 4; q++) c[j][q] = 0.f;

#pragma unroll
    for (int k0 = 0; k0 < 128; k0 += 16) {
        uint32_t a0, a1, a2, a3;
        LDSM_X4(a0, a1, a2, a3, a_base + k0 * 2);
#pragma unroll
        for (int np = 0; np < 8; np++) {
            uint32_t b0, b1, b2, b3;
            LDSM_X4(b0, b1, b2, b3, b_base + (np * 16 * SMS + k0) * 2);
            MMA16816(c[2 * np],     a0, a1, a2, a3, b0, b1);
            MMA16816(c[2 * np + 1], a0, a1, a2, a3, b2, b3);
        }
    }

    const int g = lane >> 2, t = lane & 3;
    const int rowA = row0 + r0 + g;
    const int rowB = rowA + 8;
#pragma unroll
    for (int j = 0; j < 16; j++) {
        __half2 h01 = __floats2half2_rn(c[j][0], c[j][1]);
        __half2 h23 = __floats2half2_rn(c[j][2], c[j][3]);
        int col = j * 8 + 2 * t;
        if (rowA < n_rows)
            *reinterpret_cast<__half2*>(&g_Th[(size_t)rowA * DIM + col]) = h01;
        if (rowB < n_rows)
            *reinterpret_cast<__half2*>(&g_Th[(size_t)rowB * DIM + col]) = h23;
    }
}

// ---------------------------------------------------------------------------
// hist: vectorized degree count (g_cnt starts zero; scan self-clears it)
// ---------------------------------------------------------------------------
__global__ void hist_kernel(const int* __restrict__ dst, int n_edges)
{
    int i = blockIdx.x * blockDim.x + threadIdx.x;
    int e0 = i * 4;
    if (e0 + 4 <= n_edges) {
        int4 d4 = *reinterpret_cast<const int4*>(dst + e0);
        atomicAdd(&g_cnt[d4.x], 1u);
        atomicAdd(&g_cnt[d4.y], 1u);
        atomicAdd(&g_cnt[d4.z], 1u);
        atomicAdd(&g_cnt[d4.w], 1u);
    } else {
        for (int e = e0; e < n_edges; e++) atomicAdd(&g_cnt[dst[e]], 1u);
    }
}

// ---------------------------------------------------------------------------
// Single-kernel exclusive scan with decoupled lookback. Also self-clears
// g_cnt for the next graph replay. g_state is zeroed by bucket_kernel.
// flag: 0 = invalid, 1 = block aggregate, 2 = inclusive prefix.
// ---------------------------------------------------------------------------
__global__ __launch_bounds__(1024)
void scan_kernel(int n)
{
    __shared__ unsigned wsum[32];
    __shared__ unsigned sbase;
    const int t    = threadIdx.x;
    const int lane = t & 31;
    const int warp = t >> 5;
    const int bid  = blockIdx.x;
    int i = bid * 1024 + t;

    unsigned v = (i < n) ? g_cnt[i] : 0u;
    if (i < n) g_cnt[i] = 0u;   // self-clear for next replay (hist is stream-ordered after)

    // warp inclusive scan
    unsigned x = v;
#pragma unroll
    for (int o = 1; o < 32; o <<= 1) {
        unsigned y = __shfl_up_sync(0xffffffffu, x, o);
        if (lane >= o) x += y;
    }
    if (lane == 31) wsum[warp] = x;
    __syncthreads();
    if (warp == 0) {
        unsigned s = wsum[lane];
#pragma unroll
        for (int o = 1; o < 32; o <<= 1) {
            unsigned y = __shfl_up_sync(0xffffffffu, s, o);
            if (lane >= o) s += y;
        }
        wsum[lane] = s;
    }
    __syncthreads();
    unsigned wbase = (warp > 0) ? wsum[warp - 1] : 0u;
    unsigned incl  = x + wbase;          // inclusive within block
    unsigned total = wsum[31];           // block total

    // decoupled lookback (thread 0); single-word packed publish => no fence needed
    if (t == 0) {
        if (bid == 0) {
            atomicExch(&g_state[0], (2ULL << 32) | (unsigned long long)total);
            sbase = 0u;
        } else {
            atomicExch(&g_state[bid], (1ULL << 32) | (unsigned long long)total);
            unsigned run = 0;
            int p = bid - 1;
            while (p >= 0) {
                unsigned long long s;
                do { s = atomicAdd(&g_state[p], 0ULL); } while ((s >> 32) == 0ULL);
                run += (unsigned)s;
                if ((s >> 32) == 2ULL) break;
                p--;
            }
            atomicExch(&g_state[bid], (2ULL << 32) | (unsigned long long)(run + total));
            sbase = run;
        }
    }
    __syncthreads();

    if (i < n) {
        unsigned o = incl - v + sbase;   // exclusive global prefix
        g_off[i] = o;
        g_cur[i] = o;
    }
}

// ---------------------------------------------------------------------------
// bucket: scatter edges into compact sorted order; also resets g_state for
// the next replay (stream-ordered after scan has finished with it).
// ---------------------------------------------------------------------------
__global__ void bucket_kernel(const int* __restrict__ src,
                              const int* __restrict__ dst,
                              const float* __restrict__ ew,
                              int n_edges)
{
    if (blockIdx.x == 0 && threadIdx.x < 256) g_state[threadIdx.x] = 0ULL;

    int i = blockIdx.x * blockDim.x + threadIdx.x;
    int e0 = i * 4;
    if (e0 + 4 <= n_edges) {
        int4   s4 = *reinterpret_cast<const int4*>(src + e0);
        int4   d4 = *reinterpret_cast<const int4*>(dst + e0);
        float4 w4 = *reinterpret_cast<const float4*>(ew + e0);
        unsigned p0 = atomicAdd(&g_cur[d4.x], 1u);
        unsigned p1 = atomicAdd(&g_cur[d4.y], 1u);
        unsigned p2 = atomicAdd(&g_cur[d4.z], 1u);
        unsigned p3 = atomicAdd(&g_cur[d4.w], 1u);
        g_sorted[p0] = make_uint2((unsigned)s4.x, __float_as_uint(w4.x));
        g_sorted[p1] = make_uint2((unsigned)s4.y, __float_as_uint(w4.y));
        g_sorted[p2] = make_uint2((unsigned)s4.z, __float_as_uint(w4.z));
        g_sorted[p3] = make_uint2((unsigned)s4.w, __float_as_uint(w4.w));
    } else {
        for (int e = e0; e < n_edges; e++) {
            int d = dst[e];
            unsigned pos = atomicAdd(&g_cur[d], 1u);
            g_sorted[pos] = make_uint2((unsigned)src[e], __float_as_uint(ew[e]));
        }
    }
}

// ---------------------------------------------------------------------------
// Aggregation: EXACT R8 champion loop — one warp per dst node, 4x uint2
// metadata broadcast loads, 4 independent uint2 gathers, 4 accumulators.
// ---------------------------------------------------------------------------
__device__ __forceinline__ void agg_one(float4& acc, unsigned srcn, unsigned wbits, int lane)
{
    uint2 h = *reinterpret_cast<const uint2*>(&g_Th[(size_t)srcn * DIM + lane * 4]);
    float w = __uint_as_float(wbits);
    float2 va = __half22float2(u32_to_h2(h.x));
    float2 vb = __half22float2(u32_to_h2(h.y));
    acc.x += va.x * w; acc.y += va.y * w; acc.z += vb.x * w; acc.w += vb.y * w;
}

__global__ __launch_bounds__(256)
void agg_kernel(float* __restrict__ out, int n_nodes, int n_edges)
{
    int node = (int)((blockIdx.x * (unsigned)blockDim.x + threadIdx.x) >> 5);
    int lane = threadIdx.x & 31;
    if (node >= n_nodes) return;

    unsigned start = g_off[node];
    unsigned end   = (node + 1 < n_nodes) ? g_off[node + 1] : (unsigned)n_edges;

    float4 a0 = make_float4(0.f, 0.f, 0.f, 0.f);
    float4 a1 = a0, a2 = a0, a3 = a0;

    unsigned e = start;
    for (; e + 4 <= end; e += 4) {
        uint2 m0 = g_sorted[e + 0];
        uint2 m1 = g_sorted[e + 1];
        uint2 m2 = g_sorted[e + 2];
        uint2 m3 = g_sorted[e + 3];
        uint2 h0 = *reinterpret_cast<const uint2*>(&g_Th[(size_t)m0.x * DIM + lane * 4]);
        uint2 h1 = *reinterpret_cast<const uint2*>(&g_Th[(size_t)m1.x * DIM + lane * 4]);
        uint2 h2 = *reinterpret_cast<const uint2*>(&g_Th[(size_t)m2.x * DIM + lane * 4]);
        uint2 h3 = *reinterpret_cast<const uint2*>(&g_Th[(size_t)m3.x * DIM + lane * 4]);
        float w0 = __uint_as_float(m0.y), w1 = __uint_as_float(m1.y);
        float w2 = __uint_as_float(m2.y), w3 = __uint_as_float(m3.y);
        float2 t;
        t = __half22float2(u32_to_h2(h0.x)); a0.x += t.x * w0; a0.y += t.y * w0;
        t = __half22float2(u32_to_h2(h0.y)); a0.z += t.x * w0; a0.w += t.y * w0;
        t = __half22float2(u32_to_h2(h1.x)); a1.x += t.x * w1; a1.y += t.y * w1;
        t = __half22float2(u32_to_h2(h1.y)); a1.z += t.x * w1; a1.w += t.y * w1;
        t = __half22float2(u32_to_h2(h2.x)); a2.x += t.x * w2; a2.y += t.y * w2;
        t = __half22float2(u32_to_h2(h2.y)); a2.z += t.x * w2; a2.w += t.y * w2;
        t = __half22float2(u32_to_h2(h3.x)); a3.x += t.x * w3; a3.y += t.y * w3;
        t = __half22float2(u32_to_h2(h3.y)); a3.z += t.x * w3; a3.w += t.y * w3;
    }
    for (; e < end; e++) agg_one(a0, g_sorted[e].x, g_sorted[e].y, lane);

    float4 r;
    r.x = (a0.x + a1.x) + (a2.x + a3.x);
    r.y = (a0.y + a1.y) + (a2.y + a3.y);
    r.z = (a0.z + a1.z) + (a2.z + a3.z);
    r.w = (a0.w + a1.w) + (a2.w + a3.w);
    *reinterpret_cast<float4*>(&out[(size_t)node * DIM + lane * 4]) = r;
}

// ---------------------------------------------------------------------------
// Launch: GEMM on side stream; 3-node sort chain on main (no memset, 1 scan).
// ---------------------------------------------------------------------------
extern "C" void kernel_launch(void* const* d_in, const int* in_sizes, int n_in,
                              void* d_out, int out_size)
{
    const float* node_emb = (const float*)d_in[0];
    const float* ew       = (const float*)d_in[1];
    const int*   src      = (const int*)d_in[2];
    const int*   dst      = (const int*)d_in[3];
    const float* W        = (const float*)d_in[4];
    float*       out      = (float*)d_out;

    const int n_nodes = in_sizes[0] / DIM;
    const int n_edges = in_sizes[1];

    cudaStream_t s;
    cudaStreamCreateWithFlags(&s, cudaStreamNonBlocking);
    cudaEvent_t evFork, evJoin;
    cudaEventCreateWithFlags(&evFork, cudaEventDisableTiming);
    cudaEventCreateWithFlags(&evJoin, cudaEventDisableTiming);

    cudaEventRecord(evFork, 0);
    cudaStreamWaitEvent(s, evFork, 0);

    // --- side stream: tensor-core transform (exact R8) ---
    const int smem_bytes = 2 * 128 * SMS * (int)sizeof(__half);  // 69632
    cudaFuncSetAttribute(transform_mma_kernel,
                         cudaFuncAttributeMaxDynamicSharedMemorySize, smem_bytes);
    int gemm_blocks = (n_nodes + 127) / 128;
    transform_mma_kernel<<<gemm_blocks, 256, smem_bytes, s>>>(node_emb, W, n_nodes);
    cudaEventRecord(evJoin, s);

    // --- main stream: 3-node sort chain (memset & scan3 eliminated) ---
    int eb4 = (n_edges / 4 + 255) / 256 + 1;
    hist_kernel<<<eb4, 256>>>(dst, n_edges);
    int nchunks = (n_nodes + 1023) / 1024;
    scan_kernel<<<nchunks, 1024>>>(n_nodes);
    bucket_kernel<<<eb4, 256>>>(src, dst, ew, n_edges);

    cudaStreamWaitEvent(0, evJoin, 0);
    int ab = (n_nodes * 32 + 255) / 256;
    agg_kernel<<<ab, 256>>>(out, n_nodes, n_edges);

    cudaStreamCaptureStatus cap = cudaStreamCaptureStatusNone;
    cudaStreamIsCapturing(s, &cap);
    if (cap == cudaStreamCaptureStatusNone) {
        cudaEventDestroy(evFork);
        cudaEventDestroy(evJoin);
        cudaStreamDestroy(s);
    }
}

// round 16
// speedup vs baseline: 1.0155x; 1.0015x over previous
#include <cuda_runtime.h>
#include <cuda_fp16.h>
#include <cstdint>
#include <cstring>

#define N_NODES_MAX 100000
#define EDGE_MAX    1600000
#define DIM 128

// bit-cast helpers (fold to register moves)
__device__ __forceinline__ unsigned h2_to_u32(__half2 h) {
    unsigned u; memcpy(&u, &h, 4); return u;
}
__device__ __forceinline__ __half2 u32_to_h2(unsigned u) {
    __half2 h; memcpy(&h, &u, 4); return h;
}
__device__ __forceinline__ uint32_t smem_u32(const void* p) {
    uint32_t a;
    asm("{ .reg .u64 t; cvta.to.shared.u64 t, %1; cvt.u32.u64 %0, t; }" : "=r"(a) : "l"(p));
    return a;
}

#define LDSM_X4(r0, r1, r2, r3, addr)                                         \
    asm volatile("ldmatrix.sync.aligned.m8n8.x4.shared.b16 {%0,%1,%2,%3}, [%4];" \
                 : "=r"(r0), "=r"(r1), "=r"(r2), "=r"(r3) : "r"(addr))

#define MMA16816(c, a0, a1, a2, a3, b0, b1)                                   \
    asm volatile("mma.sync.aligned.m16n8k16.row.col.f32.f16.f16.f32 "         \
                 "{%0,%1,%2,%3}, {%4,%5,%6,%7}, {%8,%9}, {%0,%1,%2,%3};"      \
                 : "+f"(c[0]), "+f"(c[1]), "+f"(c[2]), "+f"(c[3])             \
                 : "r"(a0), "r"(a1), "r"(a2), "r"(a3), "r"(b0), "r"(b1))

// scratch (allocation-free rule: __device__ globals)
__device__ __half   g_Th[(size_t)N_NODES_MAX * DIM];  // transformed features (fp16)
__device__ unsigned g_cnt[N_NODES_MAX];
__device__ unsigned g_off[N_NODES_MAX];
__device__ unsigned g_cur[N_NODES_MAX];
__device__ unsigned g_bsum[256];
__device__ uint2    g_sorted[EDGE_MAX];               // (src, weight_bits) sorted by dst

// ---------------------------------------------------------------------------
// Kernel 1: T = node_emb @ W^T via HMMA (fp16 in, f32 acc, fp16 out). EXACT R8.
// ---------------------------------------------------------------------------
#define SMS 136  // smem row stride in halves

__global__ __launch_bounds__(256, 2)
void transform_mma_kernel(const float* __restrict__ E, const float* __restrict__ W, int n_rows)
{
    extern __shared__ __half sm[];
    __half* As = sm;               // [128][SMS]
    __half* Ws = sm + 128 * SMS;   // [128][SMS]

    const int tid  = threadIdx.x;
    const int row0 = blockIdx.x * 128;

#pragma unroll
    for (int i = 0; i < 16; i++) {
        int idx = tid + i * 256;
        int r   = idx >> 5;
        int c4  = idx & 31;
        float4 v = make_float4(0.f, 0.f, 0.f, 0.f);
        int er = row0 + r;
        if (er < n_rows) v = *reinterpret_cast<const float4*>(&E[(size_t)er * DIM + c4 * 4]);
        uint2 ue = make_uint2(h2_to_u32(__floats2half2_rn(v.x, v.y)),
                              h2_to_u32(__floats2half2_rn(v.z, v.w)));
        *reinterpret_cast<uint2*>(&As[r * SMS + c4 * 4]) = ue;

        float4 wv = *reinterpret_cast<const float4*>(&W[(size_t)r * DIM + c4 * 4]);
        uint2 uw = make_uint2(h2_to_u32(__floats2half2_rn(wv.x, wv.y)),
                              h2_to_u32(__floats2half2_rn(wv.z, wv.w)));
        *reinterpret_cast<uint2*>(&Ws[r * SMS + c4 * 4]) = uw;
    }
    __syncthreads();

    const int lane = tid & 31;
    const int warp = tid >> 5;
    const int r0   = warp * 16;

    uint32_t a_base = smem_u32(&As[(r0 + (lane & 15)) * SMS + ((lane >> 4) * 8)]);
    int brow = (lane & 7) + ((lane & 16) ? 8 : 0);
    int bcol = ((lane >> 3) & 1) * 8;
    uint32_t b_base = smem_u32(&Ws[brow * SMS + bcol]);

    float c[16][4];
#pragma unroll
    for (int j = 0; j < 16; j++)
#pragma unroll
        for (int q = 0; q < 4; q++) c[j][q] = 0.f;

#pragma unroll
    for (int k0 = 0; k0 < 128; k0 += 16) {
        uint32_t a0, a1, a2, a3;
        LDSM_X4(a0, a1, a2, a3, a_base + k0 * 2);
#pragma unroll
        for (int np = 0; np < 8; np++) {
            uint32_t b0, b1, b2, b3;
            LDSM_X4(b0, b1, b2, b3, b_base + (np * 16 * SMS + k0) * 2);
            MMA16816(c[2 * np],     a0, a1, a2, a3, b0, b1);
            MMA16816(c[2 * np + 1], a0, a1, a2, a3, b2, b3);
        }
    }

    const int g = lane >> 2, t = lane & 3;
    const int rowA = row0 + r0 + g;
    const int rowB = rowA + 8;
#pragma unroll
    for (int j = 0; j < 16; j++) {
        __half2 h01 = __floats2half2_rn(c[j][0], c[j][1]);
        __half2 h23 = __floats2half2_rn(c[j][2], c[j][3]);
        int col = j * 8 + 2 * t;
        if (rowA < n_rows)
            *reinterpret_cast<__half2*>(&g_Th[(size_t)rowA * DIM + col]) = h01;
        if (rowB < n_rows)
            *reinterpret_cast<__half2*>(&g_Th[(size_t)rowB * DIM + col]) = h23;
    }
}

// ---------------------------------------------------------------------------
// Sort pipeline: hist (8-edge ILP) -> scan1(shuffle) -> scan3 -> bucket(8-edge)
// ---------------------------------------------------------------------------
__global__ void hist_kernel(const int* __restrict__ dst, int n_edges)
{
    int i = blockIdx.x * blockDim.x + threadIdx.x;
    int e0 = i * 8;
    if (e0 + 8 <= n_edges) {
        int4 dA = *reinterpret_cast<const int4*>(dst + e0);
        int4 dB = *reinterpret_cast<const int4*>(dst + e0 + 4);
        atomicAdd(&g_cnt[dA.x], 1u);
        atomicAdd(&g_cnt[dA.y], 1u);
        atomicAdd(&g_cnt[dA.z], 1u);
        atomicAdd(&g_cnt[dA.w], 1u);
        atomicAdd(&g_cnt[dB.x], 1u);
        atomicAdd(&g_cnt[dB.y], 1u);
        atomicAdd(&g_cnt[dB.z], 1u);
        atomicAdd(&g_cnt[dB.w], 1u);
    } else {
        for (int e = e0; e < n_edges; e++) atomicAdd(&g_cnt[dst[e]], 1u);
    }
}

__global__ __launch_bounds__(1024)
void scan1_kernel(int n)
{
    __shared__ unsigned wsum[32];
    const int t    = threadIdx.x;
    const int lane = t & 31;
    const int warp = t >> 5;
    int i = blockIdx.x * 1024 + t;
    unsigned v = (i < n) ? g_cnt[i] : 0u;

    unsigned x = v;
#pragma unroll
    for (int o = 1; o < 32; o <<= 1) {
        unsigned y = __shfl_up_sync(0xffffffffu, x, o);
        if (lane >= o) x += y;
    }
    if (lane == 31) wsum[warp] = x;
    __syncthreads();
    if (warp == 0) {
        unsigned s = wsum[lane];
#pragma unroll
        for (int o = 1; o < 32; o <<= 1) {
            unsigned y = __shfl_up_sync(0xffffffffu, s, o);
            if (lane >= o) s += y;
        }
        wsum[lane] = s;
    }
    __syncthreads();
    unsigned base = (warp > 0) ? wsum[warp - 1] : 0u;
    unsigned incl = x + base;
    if (i < n) g_off[i] = incl - v;
    if (t == 1023) g_bsum[blockIdx.x] = incl;
}

__global__ __launch_bounds__(1024)
void scan3_kernel(int n)
{
    __shared__ unsigned sbase;
    int t = threadIdx.x;
    if (t < 32) {
        unsigned s = 0;
        int bid = blockIdx.x;
        for (int b = t; b < bid; b += 32) s += g_bsum[b];
#pragma unroll
        for (int o = 16; o; o >>= 1) s += __shfl_down_sync(0xffffffffu, s, o);
        if (t == 0) sbase = s;
    }
    __syncthreads();
    int i = blockIdx.x * 1024 + t;
    if (i < n) {
        unsigned o = g_off[i] + sbase;
        g_off[i] = o;
        g_cur[i] = o;
    }
}

// bucket with 8-edge ILP: 8 independent atomics + 8 independent stores in
// flight per thread (R15 ncu: issue=2.4% -> pure ATOMG-latency exposure).
__global__ void bucket_kernel(const int* __restrict__ src,
                              const int* __restrict__ dst,
                              const float* __restrict__ ew,
                              int n_edges)
{
    int i = blockIdx.x * blockDim.x + threadIdx.x;
    int e0 = i * 8;
    if (e0 + 8 <= n_edges) {
        int4   sA = *reinterpret_cast<const int4*>(src + e0);
        int4   sB = *reinterpret_cast<const int4*>(src + e0 + 4);
        int4   dA = *reinterpret_cast<const int4*>(dst + e0);
        int4   dB = *reinterpret_cast<const int4*>(dst + e0 + 4);
        float4 wA = *reinterpret_cast<const float4*>(ew + e0);
        float4 wB = *reinterpret_cast<const float4*>(ew + e0 + 4);
        unsigned p0 = atomicAdd(&g_cur[dA.x], 1u);
        unsigned p1 = atomicAdd(&g_cur[dA.y], 1u);
        unsigned p2 = atomicAdd(&g_cur[dA.z], 1u);
        unsigned p3 = atomicAdd(&g_cur[dA.w], 1u);
        unsigned p4 = atomicAdd(&g_cur[dB.x], 1u);
        unsigned p5 = atomicAdd(&g_cur[dB.y], 1u);
        unsigned p6 = atomicAdd(&g_cur[dB.z], 1u);
        unsigned p7 = atomicAdd(&g_cur[dB.w], 1u);
        g_sorted[p0] = make_uint2((unsigned)sA.x, __float_as_uint(wA.x));
        g_sorted[p1] = make_uint2((unsigned)sA.y, __float_as_uint(wA.y));
        g_sorted[p2] = make_uint2((unsigned)sA.z, __float_as_uint(wA.z));
        g_sorted[p3] = make_uint2((unsigned)sA.w, __float_as_uint(wA.w));
        g_sorted[p4] = make_uint2((unsigned)sB.x, __float_as_uint(wB.x));
        g_sorted[p5] = make_uint2((unsigned)sB.y, __float_as_uint(wB.y));
        g_sorted[p6] = make_uint2((unsigned)sB.z, __float_as_uint(wB.z));
        g_sorted[p7] = make_uint2((unsigned)sB.w, __float_as_uint(wB.w));
    } else {
        for (int e = e0; e < n_edges; e++) {
            int d = dst[e];
            unsigned pos = atomicAdd(&g_cur[d], 1u);
            g_sorted[pos] = make_uint2((unsigned)src[e], __float_as_uint(ew[e]));
        }
    }
}

// ---------------------------------------------------------------------------
// Aggregation: EXACT R8 champion loop — one warp per dst node, 4x uint2
// metadata broadcast loads, 4 independent uint2 gathers, 4 accumulators.
// ---------------------------------------------------------------------------
__device__ __forceinline__ void agg_one(float4& acc, unsigned srcn, unsigned wbits, int lane)
{
    uint2 h = *reinterpret_cast<const uint2*>(&g_Th[(size_t)srcn * DIM + lane * 4]);
    float w = __uint_as_float(wbits);
    float2 va = __half22float2(u32_to_h2(h.x));
    float2 vb = __half22float2(u32_to_h2(h.y));
    acc.x += va.x * w; acc.y += va.y * w; acc.z += vb.x * w; acc.w += vb.y * w;
}

__global__ __launch_bounds__(256)
void agg_kernel(float* __restrict__ out, int n_nodes, int n_edges)
{
    int node = (int)((blockIdx.x * (unsigned)blockDim.x + threadIdx.x) >> 5);
    int lane = threadIdx.x & 31;
    if (node >= n_nodes) return;

    unsigned start = g_off[node];
    unsigned end   = (node + 1 < n_nodes) ? g_off[node + 1] : (unsigned)n_edges;

    float4 a0 = make_float4(0.f, 0.f, 0.f, 0.f);
    float4 a1 = a0, a2 = a0, a3 = a0;

    unsigned e = start;
    for (; e + 4 <= end; e += 4) {
        uint2 m0 = g_sorted[e + 0];
        uint2 m1 = g_sorted[e + 1];
        uint2 m2 = g_sorted[e + 2];
        uint2 m3 = g_sorted[e + 3];
        uint2 h0 = *reinterpret_cast<const uint2*>(&g_Th[(size_t)m0.x * DIM + lane * 4]);
        uint2 h1 = *reinterpret_cast<const uint2*>(&g_Th[(size_t)m1.x * DIM + lane * 4]);
        uint2 h2 = *reinterpret_cast<const uint2*>(&g_Th[(size_t)m2.x * DIM + lane * 4]);
        uint2 h3 = *reinterpret_cast<const uint2*>(&g_Th[(size_t)m3.x * DIM + lane * 4]);
        float w0 = __uint_as_float(m0.y), w1 = __uint_as_float(m1.y);
        float w2 = __uint_as_float(m2.y), w3 = __uint_as_float(m3.y);
        float2 t;
        t = __half22float2(u32_to_h2(h0.x)); a0.x += t.x * w0; a0.y += t.y * w0;
        t = __half22float2(u32_to_h2(h0.y)); a0.z += t.x * w0; a0.w += t.y * w0;
        t = __half22float2(u32_to_h2(h1.x)); a1.x += t.x * w1; a1.y += t.y * w1;
        t = __half22float2(u32_to_h2(h1.y)); a1.z += t.x * w1; a1.w += t.y * w1;
        t = __half22float2(u32_to_h2(h2.x)); a2.x += t.x * w2; a2.y += t.y * w2;
        t = __half22float2(u32_to_h2(h2.y)); a2.z += t.x * w2; a2.w += t.y * w2;
        t = __half22float2(u32_to_h2(h3.x)); a3.x += t.x * w3; a3.y += t.y * w3;
        t = __half22float2(u32_to_h2(h3.y)); a3.z += t.x * w3; a3.w += t.y * w3;
    }
    for (; e < end; e++) agg_one(a0, g_sorted[e].x, g_sorted[e].y, lane);

    float4 r;
    r.x = (a0.x + a1.x) + (a2.x + a3.x);
    r.y = (a0.y + a1.y) + (a2.y + a3.y);
    r.z = (a0.z + a1.z) + (a2.z + a3.z);
    r.w = (a0.w + a1.w) + (a2.w + a3.w);
    *reinterpret_cast<float4*>(&out[(size_t)node * DIM + lane * 4]) = r;
}

// ---------------------------------------------------------------------------
// Launch: GEMM on side stream overlapped with sort chain (fork/join).
// ---------------------------------------------------------------------------
extern "C" void kernel_launch(void* const* d_in, const int* in_sizes, int n_in,
                              void* d_out, int out_size)
{
    const float* node_emb = (const float*)d_in[0];
    const float* ew       = (const float*)d_in[1];
    const int*   src      = (const int*)d_in[2];
    const int*   dst      = (const int*)d_in[3];
    const float* W        = (const float*)d_in[4];
    float*       out      = (float*)d_out;

    const int n_nodes = in_sizes[0] / DIM;
    const int n_edges = in_sizes[1];

    void* cnt_ptr = nullptr;
    cudaGetSymbolAddress(&cnt_ptr, g_cnt);

    cudaStream_t s;
    cudaStreamCreateWithFlags(&s, cudaStreamNonBlocking);
    cudaEvent_t evFork, evJoin;
    cudaEventCreateWithFlags(&evFork, cudaEventDisableTiming);
    cudaEventCreateWithFlags(&evJoin, cudaEventDisableTiming);

    cudaEventRecord(evFork, 0);
    cudaStreamWaitEvent(s, evFork, 0);

    // --- side stream: tensor-core transform (exact R8) ---
    const int smem_bytes = 2 * 128 * SMS * (int)sizeof(__half);  // 69632
    cudaFuncSetAttribute(transform_mma_kernel,
                         cudaFuncAttributeMaxDynamicSharedMemorySize, smem_bytes);
    int gemm_blocks = (n_nodes + 127) / 128;
    transform_mma_kernel<<<gemm_blocks, 256, smem_bytes, s>>>(node_emb, W, n_nodes);
    cudaEventRecord(evJoin, s);

    // --- main stream: sort pipeline (8-edge ILP in hist & bucket) ---
    cudaMemsetAsync(cnt_ptr, 0, (size_t)n_nodes * sizeof(unsigned));
    int eb8 = (n_edges / 8 + 255) / 256 + 1;
    hist_kernel<<<eb8, 256>>>(dst, n_edges);
    int nchunks = (n_nodes + 1023) / 1024;
    scan1_kernel<<<nchunks, 1024>>>(n_nodes);
    scan3_kernel<<<nchunks, 1024>>>(n_nodes);
    bucket_kernel<<<eb8, 256>>>(src, dst, ew, n_edges);

    cudaStreamWaitEvent(0, evJoin, 0);
    int ab = (n_nodes * 32 + 255) / 256;
    agg_kernel<<<ab, 256>>>(out, n_nodes, n_edges);

    cudaStreamCaptureStatus cap = cudaStreamCaptureStatusNone;
    cudaStreamIsCapturing(s, &cap);
    if (cap == cudaStreamCaptureStatusNone) {
        cudaEventDestroy(evFork);
        cudaEventDestroy(evJoin);
        cudaStreamDestroy(s);
    }
}

// round 17
// speedup vs baseline: 1.0246x; 1.0090x over previous
#include <cuda_runtime.h>
#include <cuda_fp16.h>
#include <cstdint>
#include <cstring>

#define N_NODES_MAX 100000
#define EDGE_MAX    1600000
#define DIM 128

// bit-cast helpers (fold to register moves)
__device__ __forceinline__ unsigned h2_to_u32(__half2 h) {
    unsigned u; memcpy(&u, &h, 4); return u;
}
__device__ __forceinline__ __half2 u32_to_h2(unsigned u) {
    __half2 h; memcpy(&h, &u, 4); return h;
}
__device__ __forceinline__ uint32_t smem_u32(const void* p) {
    uint32_t a;
    asm("{ .reg .u64 t; cvta.to.shared.u64 t, %1; cvt.u32.u64 %0, t; }" : "=r"(a) : "l"(p));
    return a;
}

#define LDSM_X4(r0, r1, r2, r3, addr)                                         \
    asm volatile("ldmatrix.sync.aligned.m8n8.x4.shared.b16 {%0,%1,%2,%3}, [%4];" \
                 : "=r"(r0), "=r"(r1), "=r"(r2), "=r"(r3) : "r"(addr))

#define MMA16816(c, a0, a1, a2, a3, b0, b1)                                   \
    asm volatile("mma.sync.aligned.m16n8k16.row.col.f32.f16.f16.f32 "         \
                 "{%0,%1,%2,%3}, {%4,%5,%6,%7}, {%8,%9}, {%0,%1,%2,%3};"      \
                 : "+f"(c[0]), "+f"(c[1]), "+f"(c[2]), "+f"(c[3])             \
                 : "r"(a0), "r"(a1), "r"(a2), "r"(a3), "r"(b0), "r"(b1))

// scratch (allocation-free rule: __device__ globals)
__device__ __half   g_Th[(size_t)N_NODES_MAX * DIM];  // transformed features (fp16)
__device__ unsigned g_cnt[N_NODES_MAX];
__device__ unsigned g_off[N_NODES_MAX];
__device__ unsigned g_cur[N_NODES_MAX];
__device__ unsigned g_bsum[256];
__device__ uint2    g_sorted[EDGE_MAX];               // (src, weight_bits) sorted by dst

// ---------------------------------------------------------------------------
// Kernel 1: T = node_emb @ W^T via HMMA (fp16 in, f32 acc, fp16 out). EXACT R8.
// ---------------------------------------------------------------------------
#define SMS 136  // smem row stride in halves

__global__ __launch_bounds__(256, 2)
void transform_mma_kernel(const float* __restrict__ E, const float* __restrict__ W, int n_rows)
{
    extern __shared__ __half sm[];
    __half* As = sm;               // [128][SMS]
    __half* Ws = sm + 128 * SMS;   // [128][SMS]

    const int tid  = threadIdx.x;
    const int row0 = blockIdx.x * 128;

#pragma unroll
    for (int i = 0; i < 16; i++) {
        int idx = tid + i * 256;
        int r   = idx >> 5;
        int c4  = idx & 31;
        float4 v = make_float4(0.f, 0.f, 0.f, 0.f);
        int er = row0 + r;
        if (er < n_rows) v = *reinterpret_cast<const float4*>(&E[(size_t)er * DIM + c4 * 4]);
        uint2 ue = make_uint2(h2_to_u32(__floats2half2_rn(v.x, v.y)),
                              h2_to_u32(__floats2half2_rn(v.z, v.w)));
        *reinterpret_cast<uint2*>(&As[r * SMS + c4 * 4]) = ue;

        float4 wv = *reinterpret_cast<const float4*>(&W[(size_t)r * DIM + c4 * 4]);
        uint2 uw = make_uint2(h2_to_u32(__floats2half2_rn(wv.x, wv.y)),
                              h2_to_u32(__floats2half2_rn(wv.z, wv.w)));
        *reinterpret_cast<uint2*>(&Ws[r * SMS + c4 * 4]) = uw;
    }
    __syncthreads();

    const int lane = tid & 31;
    const int warp = tid >> 5;
    const int r0   = warp * 16;

    uint32_t a_base = smem_u32(&As[(r0 + (lane & 15)) * SMS + ((lane >> 4) * 8)]);
    int brow = (lane & 7) + ((lane & 16) ? 8 : 0);
    int bcol = ((lane >> 3) & 1) * 8;
    uint32_t b_base = smem_u32(&Ws[brow * SMS + bcol]);

    float c[16][4];
#pragma unroll
    for (int j = 0; j < 16; j++)
#pragma unroll
        for (int q = 0; q < 4; q++) c[j][q] = 0.f;

#pragma unroll
    for (int k0 = 0; k0 < 128; k0 += 16) {
        uint32_t a0, a1, a2, a3;
        LDSM_X4(a0, a1, a2, a3, a_base + k0 * 2);
#pragma unroll
        for (int np = 0; np < 8; np++) {
            uint32_t b0, b1, b2, b3;
            LDSM_X4(b0, b1, b2, b3, b_base + (np * 16 * SMS + k0) * 2);
            MMA16816(c[2 * np],     a0, a1, a2, a3, b0, b1);
            MMA16816(c[2 * np + 1], a0, a1, a2, a3, b2, b3);
        }
    }

    const int g = lane >> 2, t = lane & 3;
    const int rowA = row0 + r0 + g;
    const int rowB = rowA + 8;
#pragma unroll
    for (int j = 0; j < 16; j++) {
        __half2 h01 = __floats2half2_rn(c[j][0], c[j][1]);
        __half2 h23 = __floats2half2_rn(c[j][2], c[j][3]);
        int col = j * 8 + 2 * t;
        if (rowA < n_rows)
            *reinterpret_cast<__half2*>(&g_Th[(size_t)rowA * DIM + col]) = h01;
        if (rowB < n_rows)
            *reinterpret_cast<__half2*>(&g_Th[(size_t)rowB * DIM + col]) = h23;
    }
}

// ---------------------------------------------------------------------------
// Sort pipeline. hist/bucket: ILP-8 via TWO dense 4-edge groups per thread,
// drawn from opposite halves of the edge array (coalescing preserved: within
// a warp each of the two load streams has dense 16B stride).
// ---------------------------------------------------------------------------
__global__ void hist_kernel(const int* __restrict__ dst, int n_edges)
{
    const int G  = n_edges >> 2;        // full 4-edge groups
    const int Gh = (G + 1) >> 1;        // first-half group count
    int i = blockIdx.x * blockDim.x + threadIdx.x;

    if (i == 0) {                       // scalar tail (<4 edges)
        for (int e = G * 4; e < n_edges; e++) atomicAdd(&g_cnt[dst[e]], 1u);
    }
    if (i >= Gh) return;

    int4 dA = *reinterpret_cast<const int4*>(dst + i * 4);
    const bool hasB = (i + Gh) < G;
    int4 dB;
    if (hasB) dB = *reinterpret_cast<const int4*>(dst + (i + Gh) * 4);

    atomicAdd(&g_cnt[dA.x], 1u);
    atomicAdd(&g_cnt[dA.y], 1u);
    atomicAdd(&g_cnt[dA.z], 1u);
    atomicAdd(&g_cnt[dA.w], 1u);
    if (hasB) {
        atomicAdd(&g_cnt[dB.x], 1u);
        atomicAdd(&g_cnt[dB.y], 1u);
        atomicAdd(&g_cnt[dB.z], 1u);
        atomicAdd(&g_cnt[dB.w], 1u);
    }
}

__global__ __launch_bounds__(1024)
void scan1_kernel(int n)
{
    __shared__ unsigned wsum[32];
    const int t    = threadIdx.x;
    const int lane = t & 31;
    const int warp = t >> 5;
    int i = blockIdx.x * 1024 + t;
    unsigned v = (i < n) ? g_cnt[i] : 0u;

    unsigned x = v;
#pragma unroll
    for (int o = 1; o < 32; o <<= 1) {
        unsigned y = __shfl_up_sync(0xffffffffu, x, o);
        if (lane >= o) x += y;
    }
    if (lane == 31) wsum[warp] = x;
    __syncthreads();
    if (warp == 0) {
        unsigned s = wsum[lane];
#pragma unroll
        for (int o = 1; o < 32; o <<= 1) {
            unsigned y = __shfl_up_sync(0xffffffffu, s, o);
            if (lane >= o) s += y;
        }
        wsum[lane] = s;
    }
    __syncthreads();
    unsigned base = (warp > 0) ? wsum[warp - 1] : 0u;
    unsigned incl = x + base;
    if (i < n) g_off[i] = incl - v;
    if (t == 1023) g_bsum[blockIdx.x] = incl;
}

__global__ __launch_bounds__(1024)
void scan3_kernel(int n)
{
    __shared__ unsigned sbase;
    int t = threadIdx.x;
    if (t < 32) {
        unsigned s = 0;
        int bid = blockIdx.x;
        for (int b = t; b < bid; b += 32) s += g_bsum[b];
#pragma unroll
        for (int o = 16; o; o >>= 1) s += __shfl_down_sync(0xffffffffu, s, o);
        if (t == 0) sbase = s;
    }
    __syncthreads();
    int i = blockIdx.x * 1024 + t;
    if (i < n) {
        unsigned o = g_off[i] + sbase;
        g_off[i] = o;
        g_cur[i] = o;
    }
}

__global__ void bucket_kernel(const int* __restrict__ src,
                              const int* __restrict__ dst,
                              const float* __restrict__ ew,
                              int n_edges)
{
    const int G  = n_edges >> 2;
    const int Gh = (G + 1) >> 1;
    int i = blockIdx.x * blockDim.x + threadIdx.x;

    if (i == 0) {                       // scalar tail (<4 edges)
        for (int e = G * 4; e < n_edges; e++) {
            int d = dst[e];
            unsigned pos = atomicAdd(&g_cur[d], 1u);
            g_sorted[pos] = make_uint2((unsigned)src[e], __float_as_uint(ew[e]));
        }
    }
    if (i >= Gh) return;

    int eA = i * 4;
    int4   sA = *reinterpret_cast<const int4*>(src + eA);
    int4   dA = *reinterpret_cast<const int4*>(dst + eA);
    float4 wA = *reinterpret_cast<const float4*>(ew + eA);

    const bool hasB = (i + Gh) < G;
    int4 sB, dB; float4 wB;
    if (hasB) {
        int eB = (i + Gh) * 4;
        sB = *reinterpret_cast<const int4*>(src + eB);
        dB = *reinterpret_cast<const int4*>(dst + eB);
        wB = *reinterpret_cast<const float4*>(ew + eB);
    }

    // 8 independent atomics in flight
    unsigned p0 = atomicAdd(&g_cur[dA.x], 1u);
    unsigned p1 = atomicAdd(&g_cur[dA.y], 1u);
    unsigned p2 = atomicAdd(&g_cur[dA.z], 1u);
    unsigned p3 = atomicAdd(&g_cur[dA.w], 1u);
    unsigned p4 = 0, p5 = 0, p6 = 0, p7 = 0;
    if (hasB) {
        p4 = atomicAdd(&g_cur[dB.x], 1u);
        p5 = atomicAdd(&g_cur[dB.y], 1u);
        p6 = atomicAdd(&g_cur[dB.z], 1u);
        p7 = atomicAdd(&g_cur[dB.w], 1u);
    }

    g_sorted[p0] = make_uint2((unsigned)sA.x, __float_as_uint(wA.x));
    g_sorted[p1] = make_uint2((unsigned)sA.y, __float_as_uint(wA.y));
    g_sorted[p2] = make_uint2((unsigned)sA.z, __float_as_uint(wA.z));
    g_sorted[p3] = make_uint2((unsigned)sA.w, __float_as_uint(wA.w));
    if (hasB) {
        g_sorted[p4] = make_uint2((unsigned)sB.x, __float_as_uint(wB.x));
        g_sorted[p5] = make_uint2((unsigned)sB.y, __float_as_uint(wB.y));
        g_sorted[p6] = make_uint2((unsigned)sB.z, __float_as_uint(wB.z));
        g_sorted[p7] = make_uint2((unsigned)sB.w, __float_as_uint(wB.w));
    }
}

// ---------------------------------------------------------------------------
// Aggregation: EXACT R8 champion loop — one warp per dst node, 4x uint2
// metadata broadcast loads, 4 independent uint2 gathers, 4 accumulators.
// ---------------------------------------------------------------------------
__device__ __forceinline__ void agg_one(float4& acc, unsigned srcn, unsigned wbits, int lane)
{
    uint2 h = *reinterpret_cast<const uint2*>(&g_Th[(size_t)srcn * DIM + lane * 4]);
    float w = __uint_as_float(wbits);
    float2 va = __half22float2(u32_to_h2(h.x));
    float2 vb = __half22float2(u32_to_h2(h.y));
    acc.x += va.x * w; acc.y += va.y * w; acc.z += vb.x * w; acc.w += vb.y * w;
}

__global__ __launch_bounds__(256)
void agg_kernel(float* __restrict__ out, int n_nodes, int n_edges)
{
    int node = (int)((blockIdx.x * (unsigned)blockDim.x + threadIdx.x) >> 5);
    int lane = threadIdx.x & 31;
    if (node >= n_nodes) return;

    unsigned start = g_off[node];
    unsigned end   = (node + 1 < n_nodes) ? g_off[node + 1] : (unsigned)n_edges;

    float4 a0 = make_float4(0.f, 0.f, 0.f, 0.f);
    float4 a1 = a0, a2 = a0, a3 = a0;

    unsigned e = start;
    for (; e + 4 <= end; e += 4) {
        uint2 m0 = g_sorted[e + 0];
        uint2 m1 = g_sorted[e + 1];
        uint2 m2 = g_sorted[e + 2];
        uint2 m3 = g_sorted[e + 3];
        uint2 h0 = *reinterpret_cast<const uint2*>(&g_Th[(size_t)m0.x * DIM + lane * 4]);
        uint2 h1 = *reinterpret_cast<const uint2*>(&g_Th[(size_t)m1.x * DIM + lane * 4]);
        uint2 h2 = *reinterpret_cast<const uint2*>(&g_Th[(size_t)m2.x * DIM + lane * 4]);
        uint2 h3 = *reinterpret_cast<const uint2*>(&g_Th[(size_t)m3.x * DIM + lane * 4]);
        float w0 = __uint_as_float(m0.y), w1 = __uint_as_float(m1.y);
        float w2 = __uint_as_float(m2.y), w3 = __uint_as_float(m3.y);
        float2 t;
        t = __half22float2(u32_to_h2(h0.x)); a0.x += t.x * w0; a0.y += t.y * w0;
        t = __half22float2(u32_to_h2(h0.y)); a0.z += t.x * w0; a0.w += t.y * w0;
        t = __half22float2(u32_to_h2(h1.x)); a1.x += t.x * w1; a1.y += t.y * w1;
        t = __half22float2(u32_to_h2(h1.y)); a1.z += t.x * w1; a1.w += t.y * w1;
        t = __half22float2(u32_to_h2(h2.x)); a2.x += t.x * w2; a2.y += t.y * w2;
        t = __half22float2(u32_to_h2(h2.y)); a2.z += t.x * w2; a2.w += t.y * w2;
        t = __half22float2(u32_to_h2(h3.x)); a3.x += t.x * w3; a3.y += t.y * w3;
        t = __half22float2(u32_to_h2(h3.y)); a3.z += t.x * w3; a3.w += t.y * w3;
    }
    for (; e < end; e++) agg_one(a0, g_sorted[e].x, g_sorted[e].y, lane);

    float4 r;
    r.x = (a0.x + a1.x) + (a2.x + a3.x);
    r.y = (a0.y + a1.y) + (a2.y + a3.y);
    r.z = (a0.z + a1.z) + (a2.z + a3.z);
    r.w = (a0.w + a1.w) + (a2.w + a3.w);
    *reinterpret_cast<float4*>(&out[(size_t)node * DIM + lane * 4]) = r;
}

// ---------------------------------------------------------------------------
// Launch: GEMM on side stream overlapped with sort chain (fork/join).
// ---------------------------------------------------------------------------
extern "C" void kernel_launch(void* const* d_in, const int* in_sizes, int n_in,
                              void* d_out, int out_size)
{
    const float* node_emb = (const float*)d_in[0];
    const float* ew       = (const float*)d_in[1];
    const int*   src      = (const int*)d_in[2];
    const int*   dst      = (const int*)d_in[3];
    const float* W        = (const float*)d_in[4];
    float*       out      = (float*)d_out;

    const int n_nodes = in_sizes[0] / DIM;
    const int n_edges = in_sizes[1];

    void* cnt_ptr = nullptr;
    cudaGetSymbolAddress(&cnt_ptr, g_cnt);

    cudaStream_t s;
    cudaStreamCreateWithFlags(&s, cudaStreamNonBlocking);
    cudaEvent_t evFork, evJoin;
    cudaEventCreateWithFlags(&evFork, cudaEventDisableTiming);
    cudaEventCreateWithFlags(&evJoin, cudaEventDisableTiming);

    cudaEventRecord(evFork, 0);
    cudaStreamWaitEvent(s, evFork, 0);

    // --- side stream: tensor-core transform (exact R8) ---
    const int smem_bytes = 2 * 128 * SMS * (int)sizeof(__half);  // 69632
    cudaFuncSetAttribute(transform_mma_kernel,
                         cudaFuncAttributeMaxDynamicSharedMemorySize, smem_bytes);
    int gemm_blocks = (n_nodes + 127) / 128;
    transform_mma_kernel<<<gemm_blocks, 256, smem_bytes, s>>>(node_emb, W, n_nodes);
    cudaEventRecord(evJoin, s);

    // --- main stream: sort pipeline (ILP-8 hist/bucket, dense loads) ---
    cudaMemsetAsync(cnt_ptr, 0, (size_t)n_nodes * sizeof(unsigned));
    int Gh = ((n_edges >> 2) + 1) >> 1;
    int ebh = (Gh + 255) / 256;
    hist_kernel<<<ebh, 256>>>(dst, n_edges);
    int nchunks = (n_nodes + 1023) / 1024;
    scan1_kernel<<<nchunks, 1024>>>(n_nodes);
    scan3_kernel<<<nchunks, 1024>>>(n_nodes);
    bucket_kernel<<<ebh, 256>>>(src, dst, ew, n_edges);

    cudaStreamWaitEvent(0, evJoin, 0);
    int ab = (n_nodes * 32 + 255) / 256;
    agg_kernel<<<ab, 256>>>(out, n_nodes, n_edges);

    cudaStreamCaptureStatus cap = cudaStreamCaptureStatusNone;
    cudaStreamIsCapturing(s, &cap);
    if (cap == cudaStreamCaptureStatusNone) {
        cudaEventDestroy(evFork);
        cudaEventDestroy(evJoin);
        cudaStreamDestroy(s);
    }
}